// round 4
// baseline (speedup 1.0000x reference)
#include <cuda_runtime.h>
#include <cstdint>

// Kendall's tau loss via discordant-pair count (no ties in random normals):
//   loss = 4*D / (n(n-1)),  D = #{i<j : sign(p_i-p_j) != sign(t_i-t_j)}
// R4: 4 rows/thread (4 indep chains), LDS.128 feeds 2 j's x 4 rows per load,
// and accumulation split across BOTH pipes: 2 rows via LEA.HI (alu pipe),
// 2 rows via IMAD.HI.U32 (__umulhi(x,2)+c, fma pipe) -> 1.5 instr/pair/pipe.

#define TILE 256
#define NTH 64
#define NROWS 4

__device__ unsigned long long g_cnt = 0;
__device__ unsigned int g_done = 0;

__device__ __forceinline__ unsigned long long pack2(float lo, float hi) {
    unsigned long long r;
    asm("mov.b64 %0, {%1, %2};" : "=l"(r) : "f"(lo), "f"(hi));
    return r;
}

__device__ __forceinline__ unsigned int xor_word(unsigned long long a,
                                                 unsigned long long nb) {
    unsigned long long s;
    asm("add.rn.f32x2 %0, %1, %2;" : "=l"(s) : "l"(a), "l"(nb));
    unsigned int lo, hi;
    asm("mov.b64 {%0, %1}, %2;" : "=r"(lo), "=r"(hi) : "l"(s));
    return lo ^ hi;
}

// alu-pipe accumulate: LOP3 + LEA.HI
__device__ __forceinline__ void acc_alu(unsigned int& c, unsigned long long a,
                                        unsigned long long nb) {
    c += xor_word(a, nb) >> 31;
}
// fma-pipe accumulate: LOP3 + IMAD.HI.U32 (x*2 >> 32 == bit31)
__device__ __forceinline__ void acc_fma(unsigned int& c, unsigned long long a,
                                        unsigned long long nb) {
    c = __umulhi(xor_word(a, nb), 2u) + c;
}

__global__ __launch_bounds__(NTH) void kt_kernel(
    const float* __restrict__ p, const float* __restrict__ t,
    float* __restrict__ out, int n)
{
    const int ntiles = (n + TILE - 1) / TILE;

    // Linear block id -> upper-triangular (bi, bj), bj >= bi.
    int b = blockIdx.x;
    int bi = 0;
    while (b >= ntiles - bi) { b -= ntiles - bi; ++bi; }
    const int bj = bi + b;

    __shared__ __align__(16) float2 snb[TILE];  // (-p_j, -t_j)

    const int tid = threadIdx.x;
    const int jb = bj * TILE;
    const int jlim = min(TILE, n - jb);

    #pragma unroll
    for (int k = tid; k < TILE; k += NTH)
        if (k < jlim) snb[k] = make_float2(-p[jb + k], -t[jb + k]);
    __syncthreads();

    const int ib = bi * TILE;
    unsigned int c0 = 0, c1 = 0, c2 = 0, c3 = 0;

    const bool full = (jlim == TILE) && (ib + TILE <= n);

    if (full && bi != bj) {
        // Full off-diagonal tile: all pairs valid. 4 rows per thread.
        const unsigned long long a0 = pack2(p[ib + tid          ], t[ib + tid          ]);
        const unsigned long long a1 = pack2(p[ib + tid +     NTH], t[ib + tid +     NTH]);
        const unsigned long long a2 = pack2(p[ib + tid + 2 * NTH], t[ib + tid + 2 * NTH]);
        const unsigned long long a3 = pack2(p[ib + tid + 3 * NTH], t[ib + tid + 3 * NTH]);

        const ulonglong2* B2 = reinterpret_cast<const ulonglong2*>(snb);
        #pragma unroll 4
        for (int k2 = 0; k2 < TILE / 2; ++k2) {
            const ulonglong2 bb = B2[k2];   // two consecutive j's
            acc_alu(c0, a0, bb.x);  acc_alu(c1, a1, bb.x);
            acc_fma(c2, a2, bb.x);  acc_fma(c3, a3, bb.x);
            acc_alu(c0, a0, bb.y);  acc_alu(c1, a1, bb.y);
            acc_fma(c2, a2, bb.y);  acc_fma(c3, a3, bb.y);
        }
    } else if (full) {
        // Diagonal tile: local j > local i.
        const unsigned long long* B =
            reinterpret_cast<const unsigned long long*>(snb);
        #pragma unroll
        for (int r = 0; r < NROWS; ++r) {
            const int il = tid + r * NTH;
            const unsigned long long a = pack2(p[ib + il], t[ib + il]);
            unsigned int c = 0;
            #pragma unroll 4
            for (int k = il + 1; k < TILE; ++k) acc_alu(c, a, B[k]);
            c0 += c;
        }
    } else {
        // Partial tile (not hit for n=8192; kept for generality).
        const unsigned long long* B =
            reinterpret_cast<const unsigned long long*>(snb);
        for (int r = 0; r < NROWS; ++r) {
            const int i = ib + tid + r * NTH;
            if (i < n) {
                const unsigned long long a = pack2(p[i], t[i]);
                for (int k = 0; k < jlim; ++k)
                    if (jb + k > i) acc_alu(c0, a, B[k]);
            }
        }
    }

    unsigned int cnt = (c0 + c1) + (c2 + c3);

    #pragma unroll
    for (int off = 16; off > 0; off >>= 1)
        cnt += __shfl_down_sync(0xFFFFFFFFu, cnt, off);

    __shared__ unsigned int wsum[NTH / 32];
    if ((tid & 31) == 0) wsum[tid >> 5] = cnt;
    __syncthreads();

    if (tid == 0) {
        unsigned int total = 0;
        #pragma unroll
        for (int w = 0; w < NTH / 32; ++w) total += wsum[w];

        atomicAdd(&g_cnt, (unsigned long long)total);
        __threadfence();
        const unsigned int d = atomicAdd(&g_done, 1u);
        if (d == gridDim.x - 1) {
            const unsigned long long D = atomicAdd(&g_cnt, 0ULL);
            const double nn = (double)n;
            out[0] = (float)(4.0 * (double)D / (nn * (nn - 1.0)));
            g_cnt = 0ULL;   // reset for next graph replay
            g_done = 0u;
        }
    }
}

extern "C" void kernel_launch(void* const* d_in, const int* in_sizes, int n_in,
                              void* d_out, int out_size)
{
    const float* predictions = (const float*)d_in[0];
    const float* true_labels = (const float*)d_in[1];
    float* out = (float*)d_out;
    const int n = in_sizes[0];

    const int ntiles = (n + TILE - 1) / TILE;
    const int nblocks = ntiles * (ntiles + 1) / 2;

    kt_kernel<<<nblocks, NTH>>>(predictions, true_labels, out, n);
}